// round 7
// baseline (speedup 1.0000x reference)
#include <cuda_runtime.h>
#include <stdint.h>

// ======================= problem constants =======================
#define BATCH   8192
#define UNITS   1024
#define NPTS    30
#define AR      12
#define RR      64
#define NCOLS   76            // AR + RR
#define NPAD    80
#define G3      3072          // 3 * UNITS

// JAX threefry mode: 1 = partitionable (JAX >= 0.5 default), 0 = original
#define PARTITIONABLE 1

// output layout: concat(a_oh, a_prob, r_oh, r_prob), each [B, NPTS, C] row-major
#define AOH_BASE    0
#define APROB_BASE  (BATCH*NPTS*AR)                    // 2949120
#define ROH_BASE    (2*BATCH*NPTS*AR)                  // 5898240
#define RPROB_BASE  (2*BATCH*NPTS*AR + BATCH*NPTS*RR)  // 21626880

typedef unsigned long long u64;

// ======================= persistent device state =======================
__device__ float g_h[2ull * BATCH * UNITS];   // ping-pong hidden state
__device__ float g_P[NCOLS * G3];             // W_enc @ W_gru
__device__ float g_G[G3];                     // b_enc @ W_gru + b_gru
__device__ float g_Wt[NPAD * UNITS];          // transposed logits weights [80][1024]
__device__ float g_bt[NPAD];                  // concatenated bias [80]
__device__ int   g_aidx[BATCH];
__device__ int   g_ridx[BATCH];

// ======================= packed f32x2 helpers =======================
__device__ __forceinline__ u64 pack2(float lo, float hi) {
    u64 r;
    asm("mov.b64 %0, {%1, %2};" : "=l"(r) : "f"(lo), "f"(hi));
    return r;
}
__device__ __forceinline__ void fma2(u64& acc, u64 a, u64 b) {
    asm("fma.rn.f32x2 %0, %1, %2, %0;" : "+l"(acc) : "l"(a), "l"(b));
}
__device__ __forceinline__ float2 unpack2(u64 v) {
    float2 f;
    asm("mov.b64 {%0, %1}, %2;" : "=f"(f.x), "=f"(f.y) : "l"(v));
    return f;
}

// ======================= threefry-2x32 (20 rounds) =======================
__host__ __device__ __forceinline__ void threefry2x32(
    uint32_t k0, uint32_t k1, uint32_t x0, uint32_t x1,
    uint32_t& o0, uint32_t& o1)
{
    uint32_t ks2 = k0 ^ k1 ^ 0x1BD11BDAu;
    x0 += k0; x1 += k1;
#define TFR(r) { x0 += x1; x1 = (x1 << (r)) | (x1 >> (32 - (r))); x1 ^= x0; }
    TFR(13) TFR(15) TFR(26) TFR(6)   x0 += k1;  x1 += ks2 + 1u;
    TFR(17) TFR(29) TFR(16) TFR(24)  x0 += ks2; x1 += k0 + 2u;
    TFR(13) TFR(15) TFR(26) TFR(6)   x0 += k0;  x1 += k1 + 3u;
    TFR(17) TFR(29) TFR(16) TFR(24)  x0 += k1;  x1 += ks2 + 4u;
    TFR(13) TFR(15) TFR(26) TFR(6)   x0 += ks2; x1 += k0 + 5u;
#undef TFR
    o0 = x0; o1 = x1;
}

// ======================= precompute P and G (Kahan) =======================
__global__ void precompute_kernel(const float* __restrict__ Wenc,
                                  const float* __restrict__ benc,
                                  const float* __restrict__ Wgru,
                                  const float* __restrict__ bgru)
{
    int j = blockIdx.x * blockDim.x + threadIdx.x;   // 0..G3-1
    int g = blockIdx.y;                              // 0..NCOLS (last = G row)
    if (j >= G3) return;
    const float* arow = (g < NCOLS) ? (Wenc + (size_t)g * UNITS) : benc;
    float s = 0.f, c = 0.f;
    for (int k = 0; k < UNITS; k++) {
        float prod = arow[k] * Wgru[(size_t)k * G3 + j];
        float y = prod - c;
        float t = s + y;
        c = (t - s) - y;
        s = t;
    }
    if (g < NCOLS) g_P[(size_t)g * G3 + j] = s;
    else           g_G[j] = s + bgru[j];
}

// ======================= transpose logits weights (one-time) =======================
// g_Wt[x][k] = x<12 ? Wang[k][x] : x<76 ? Wrad[k][x-12] : 0
__global__ void fill_wt_kernel(const float* __restrict__ Wang, const float* __restrict__ bang,
                               const float* __restrict__ Wrad, const float* __restrict__ brad)
{
    const int x = blockIdx.x;                  // 0..79
    for (int k = threadIdx.x; k < UNITS; k += blockDim.x) {
        float v = 0.f;
        if (x < AR)         v = Wang[(size_t)k * AR + x];
        else if (x < NCOLS) v = Wrad[(size_t)k * RR + (x - AR)];
        g_Wt[(size_t)x * UNITS + k] = v;
    }
    if (threadIdx.x == 0) {
        float b = 0.f;
        if (x < AR)         b = bang[x];
        else if (x < NCOLS) b = brad[x - AR];
        g_bt[x] = b;
    }
}

// ======================= fused GEMM (h @ U_gru) + GRU cell =======================
// BM=128 x BN=32 x 3 gates, 256 threads, per-thread 8 rows x 2 cols x 3 gates.
// f32x2 pairs run along M: A row-pairs load directly as LDS.128 (broadcast),
// B values dup-packed on the ALU pipe. Double-buffered smem, 1 barrier/tile.
// NOTE: per-output-element accumulation is a single acc, ascending k -> the
// h bit-pattern is frozen; do not change the FMA order here.
#define BM 128
#define BN 32
#define KB 16

__global__ __launch_bounds__(256, 2)
void gru_step_kernel(const float* __restrict__ hin, float* __restrict__ hout,
                     const float* __restrict__ Ugru, const float* __restrict__ bgru,
                     int first)
{
    __shared__ __align__(16) float As[2][KB][BM];
    __shared__ __align__(16) float Bs[2][3][KB][BN];

    const int m0 = blockIdx.y * BM;
    const int j0 = blockIdx.x * BN;
    const int tid = threadIdx.x;
    const int tx = tid & 15;     // 0..15  -> 2 cols each
    const int ty = tid >> 4;     // 0..15  -> 8 rows each (4 f32x2 row-pairs)

    // acc[c][p]: c = gate*2 + n (6 cols), p = row-pair 0..3 (rows 2p, 2p+1)
    u64 acc[6][4];
#pragma unroll
    for (int c = 0; c < 6; c++)
#pragma unroll
        for (int p = 0; p < 4; p++) acc[c][p] = 0ull;

    // A-loader mapping: 2048 floats = 512 float4; thread loads 2 float4
    const int la_row = tid >> 2;         // 0..63
    const int la_kk  = (tid & 3) << 2;   // 0,4,8,12
    // B-loader mapping: per gate 512 floats = 256 float2; thread loads 1 float2/gate
    const int lb_kk = tid >> 4;          // 0..15
    const int lb_jj = (tid & 15) << 1;   // 0..30

    const float* pa0 = &hin[(size_t)(m0 + la_row) * UNITS + la_kk];
    const float* pa1 = &hin[(size_t)(m0 + la_row + 64) * UNITS + la_kk];
    const float* pb  = &Ugru[(size_t)lb_kk * G3 + j0 + lb_jj];

    // prologue: load tile 0 into buffer 0
    {
        float4 v0 = *(const float4*)pa0;
        float4 v1 = *(const float4*)pa1;
        As[0][la_kk + 0][la_row] = v0.x; As[0][la_kk + 1][la_row] = v0.y;
        As[0][la_kk + 2][la_row] = v0.z; As[0][la_kk + 3][la_row] = v0.w;
        As[0][la_kk + 0][la_row + 64] = v1.x; As[0][la_kk + 1][la_row + 64] = v1.y;
        As[0][la_kk + 2][la_row + 64] = v1.z; As[0][la_kk + 3][la_row + 64] = v1.w;
#pragma unroll
        for (int g = 0; g < 3; g++)
            *(float2*)&Bs[0][g][lb_kk][lb_jj] = *(const float2*)(pb + g * UNITS);
    }
    __syncthreads();

    const int NT = UNITS / KB;   // 64 tiles
    int cur = 0;
    for (int t = 0; t < NT; t++) {
        float4 va0, va1; float2 vb[3];
        const bool more = (t + 1 < NT);
        if (more) {
            const size_t koff = (size_t)(t + 1) * KB;
            va0 = *(const float4*)(pa0 + koff);
            va1 = *(const float4*)(pa1 + koff);
#pragma unroll
            for (int g = 0; g < 3; g++)
                vb[g] = *(const float2*)(pb + koff * G3 + g * UNITS);
        }

#pragma unroll
        for (int k = 0; k < KB; k++) {
            // A row-pairs: two LDS.128, broadcast within warp, no packs needed
            ulonglong2 a01 = *(const ulonglong2*)&As[cur][k][ty * 8];
            ulonglong2 a23 = *(const ulonglong2*)&As[cur][k][ty * 8 + 4];
            u64 a2[4] = { a01.x, a01.y, a23.x, a23.y };
            // B: one LDS.64 per gate + dup-pack each scalar (ALU pipe)
            u64 b2[6];
#pragma unroll
            for (int g = 0; g < 3; g++) {
                float2 b = *(const float2*)&Bs[cur][g][k][tx * 2];
                b2[g * 2 + 0] = pack2(b.x, b.x);
                b2[g * 2 + 1] = pack2(b.y, b.y);
            }
#pragma unroll
            for (int c = 0; c < 6; c++)
#pragma unroll
                for (int p = 0; p < 4; p++)
                    fma2(acc[c][p], a2[p], b2[c]);
        }

        if (more) {
            const int nxt = cur ^ 1;
            As[nxt][la_kk + 0][la_row] = va0.x; As[nxt][la_kk + 1][la_row] = va0.y;
            As[nxt][la_kk + 2][la_row] = va0.z; As[nxt][la_kk + 3][la_row] = va0.w;
            As[nxt][la_kk + 0][la_row + 64] = va1.x; As[nxt][la_kk + 1][la_row + 64] = va1.y;
            As[nxt][la_kk + 2][la_row + 64] = va1.z; As[nxt][la_kk + 3][la_row + 64] = va1.w;
#pragma unroll
            for (int g = 0; g < 3; g++)
                *(float2*)&Bs[nxt][g][lb_kk][lb_jj] = vb[g];
            __syncthreads();
            cur = nxt;
        }
    }

    // epilogue: gx gather (vectorized float2) + GRU cell
    const int jb = j0 + tx * 2;
#pragma unroll
    for (int p = 0; p < 4; p++) {
        float2 vz[2] = { unpack2(acc[0][p]), unpack2(acc[1][p]) };
        float2 vr[2] = { unpack2(acc[2][p]), unpack2(acc[3][p]) };
        float2 vn[2] = { unpack2(acc[4][p]), unpack2(acc[5][p]) };
#pragma unroll
        for (int rr = 0; rr < 2; rr++) {
            const int row = m0 + ty * 8 + p * 2 + rr;
            const float az0 = rr ? vz[0].y : vz[0].x;
            const float az1 = rr ? vz[1].y : vz[1].x;
            const float ar0 = rr ? vr[0].y : vr[0].x;
            const float ar1 = rr ? vr[1].y : vr[1].x;
            const float an0 = rr ? vn[0].y : vn[0].x;
            const float an1 = rr ? vn[1].y : vn[1].x;

            float2 pz, pr, pn;
            if (first) {
                pz = *(const float2*)&bgru[jb];
                pr = *(const float2*)&bgru[UNITS + jb];
                pn = *(const float2*)&bgru[2 * UNITS + jb];
            } else {
                const float* Pa = g_P + (size_t)g_aidx[row] * G3;
                const float* Pr = g_P + (size_t)(AR + g_ridx[row]) * G3;
                float2 a, b, c;
                a = *(const float2*)&Pa[jb];
                b = *(const float2*)&Pr[jb];
                c = *(const float2*)&g_G[jb];
                pz.x = a.x + b.x + c.x; pz.y = a.y + b.y + c.y;
                a = *(const float2*)&Pa[UNITS + jb];
                b = *(const float2*)&Pr[UNITS + jb];
                c = *(const float2*)&g_G[UNITS + jb];
                pr.x = a.x + b.x + c.x; pr.y = a.y + b.y + c.y;
                a = *(const float2*)&Pa[2 * UNITS + jb];
                b = *(const float2*)&Pr[2 * UNITS + jb];
                c = *(const float2*)&g_G[2 * UNITS + jb];
                pn.x = a.x + b.x + c.x; pn.y = a.y + b.y + c.y;
            }
            const float2 hp = *(const float2*)&hin[(size_t)row * UNITS + jb];
            const float z0 = 1.f / (1.f + expf(-(pz.x + az0)));
            const float z1 = 1.f / (1.f + expf(-(pz.y + az1)));
            const float r0 = 1.f / (1.f + expf(-(pr.x + ar0)));
            const float r1 = 1.f / (1.f + expf(-(pr.y + ar1)));
            const float n0 = tanhf(pn.x + r0 * an0);
            const float n1 = tanhf(pn.y + r1 * an1);
            float2 o;
            o.x = z0 * hp.x + (1.f - z0) * n0;
            o.y = z1 * hp.y + (1.f - z1) * n1;
            *(float2*)&hout[(size_t)row * UNITS + jb] = o;
        }
    }
}

// ======================= sampling kernel =======================
// One block handles R=8 rows. 640 threads laid out as (x=0..79, y=0..7), x<76 active.
// Dot loop vectorized via transposed weights g_Wt: bit-identical fmaf sequence
// to the original (a_i += hs[y][k+i] * W[k+i][x], 4-way split accumulators).
#define SR 8

__global__ __launch_bounds__(640)
void sample_kernel(const float* __restrict__ h,
                   float* __restrict__ out, int t,
                   uint32_t ka0, uint32_t ka1, uint32_t kr0, uint32_t kr1)
{
    __shared__ __align__(16) float hs[SR][UNITS];
    __shared__ float lg[SR][NCOLS];
    __shared__ float es[SR][NCOLS];
    __shared__ float pl[SR][NCOLS];
    __shared__ float mx[SR][2];
    __shared__ float sm[SR][2];
    __shared__ int   sidx[SR][2];

    const int tid  = threadIdx.x;
    const int row0 = blockIdx.x * SR;
    const int x = tid % 80;
    const int y = tid / 80;

    // stage h rows into smem
    for (int i = tid; i < SR * UNITS / 4; i += blockDim.x) {
        int r = i >> 8;            // /256 (=1024/4)
        int c = (i & 255) << 2;
        *(float4*)&hs[r][c] = *(const float4*)&h[(size_t)(row0 + r) * UNITS + c];
    }
    __syncthreads();

    if (x < NCOLS) {
        // logits: dot(h_row, Wt row) with 4-way partial sums (bit-exact vs original)
        const float* wt = g_Wt + (size_t)x * UNITS;
        float a0 = 0.f, a1 = 0.f, a2 = 0.f, a3 = 0.f;
#pragma unroll 4
        for (int k = 0; k < UNITS; k += 4) {
            float4 w4 = *(const float4*)&wt[k];
            float4 h4 = *(const float4*)&hs[y][k];
            a0 = fmaf(h4.x, w4.x, a0);
            a1 = fmaf(h4.y, w4.y, a1);
            a2 = fmaf(h4.z, w4.z, a2);
            a3 = fmaf(h4.w, w4.w, a3);
        }
        float l = ((a0 + a1) + (a2 + a3)) + g_bt[x];
        lg[y][x] = l;

        // gumbel noise, exact JAX formula
        const int row = row0 + y;
        uint32_t key0, key1, bits;
#if PARTITIONABLE
        uint32_t f = (x < AR) ? (uint32_t)(row * AR + x) : (uint32_t)(row * RR + (x - AR));
        if (x < AR) { key0 = ka0; key1 = ka1; } else { key0 = kr0; key1 = kr1; }
        uint32_t o0, o1;
        threefry2x32(key0, key1, 0u, f, o0, o1);
        bits = o0 ^ o1;
#else
        uint32_t f, half;
        if (x < AR) { f = (uint32_t)(row * AR + x);        half = (uint32_t)(BATCH * AR / 2); key0 = ka0; key1 = ka1; }
        else        { f = (uint32_t)(row * RR + (x - AR)); half = (uint32_t)(BATCH * RR / 2); key0 = kr0; key1 = kr1; }
        uint32_t j = (f < half) ? f : (f - half);
        uint32_t o0, o1;
        threefry2x32(key0, key1, j, j + half, o0, o1);
        bits = (f < half) ? o0 : o1;
#endif
        const float TINY = 1.17549435e-38f;
        float fl = __uint_as_float((bits >> 9) | 0x3f800000u) - 1.0f;
        float uu = fmaxf(TINY, fl + TINY);
        float gum = -logf(-logf(uu));
        pl[y][x] = gum + l;
    }
    __syncthreads();

    // per-row reductions (max logit for softmax; first-occurrence argmax of logits+gumbel)
    if (x == 0) {
        float m = lg[y][0];
        for (int i = 1; i < AR; i++) m = fmaxf(m, lg[y][i]);
        mx[y][0] = m;
        float best = pl[y][0]; int bi = 0;
        for (int i = 1; i < AR; i++) if (pl[y][i] > best) { best = pl[y][i]; bi = i; }
        sidx[y][0] = bi;
    } else if (x == 1) {
        float m = lg[y][AR];
        for (int i = AR + 1; i < NCOLS; i++) m = fmaxf(m, lg[y][i]);
        mx[y][1] = m;
        float best = pl[y][AR]; int bi = 0;
        for (int i = AR + 1; i < NCOLS; i++) if (pl[y][i] > best) { best = pl[y][i]; bi = i - AR; }
        sidx[y][1] = bi;
    }
    __syncthreads();

    if (x < NCOLS) es[y][x] = expf(lg[y][x] - mx[y][(x < AR) ? 0 : 1]);
    __syncthreads();

    if (x == 0) { float s = 0.f; for (int i = 0;  i < AR;    i++) s += es[y][i]; sm[y][0] = s; }
    else if (x == 1) { float s = 0.f; for (int i = AR; i < NCOLS; i++) s += es[y][i]; sm[y][1] = s; }
    __syncthreads();

    const int row = row0 + y;
    if (x < AR) {
        size_t o = (size_t)(row * NPTS + t) * AR + x;
        out[AOH_BASE   + o] = (x == sidx[y][0]) ? 1.0f : 0.0f;
        out[APROB_BASE + o] = es[y][x] / sm[y][0];
    } else if (x < NCOLS) {
        int c = x - AR;
        size_t o = (size_t)(row * NPTS + t) * RR + c;
        out[ROH_BASE   + o] = (c == sidx[y][1]) ? 1.0f : 0.0f;
        out[RPROB_BASE + o] = es[y][x] / sm[y][1];
    }
    if (x == 0) g_aidx[row] = sidx[y][0];
    if (x == 1) g_ridx[row] = sidx[y][1];
}

// ======================= host-side key derivation =======================
#if !PARTITIONABLE
static void orig_split(uint32_t k0, uint32_t k1, int n, uint32_t out[][2])
{
    uint32_t y0[64], y1[64];
    for (int j = 0; j < n; j++)
        threefry2x32(k0, k1, (uint32_t)j, (uint32_t)(n + j), y0[j], y1[j]);
    for (int t = 0; t < n; t++) {
        int i0 = 2 * t, i1 = 2 * t + 1;
        out[t][0] = (i0 < n) ? y0[i0] : y1[i0 - n];
        out[t][1] = (i1 < n) ? y0[i1] : y1[i1 - n];
    }
}
#endif

// ======================= launcher =======================
extern "C" void kernel_launch(void* const* d_in, const int* in_sizes, int n_in,
                              void* d_out, int out_size)
{
    const float* s    = (const float*)d_in[0];
    const float* Wenc = (const float*)d_in[1];
    const float* benc = (const float*)d_in[2];
    const float* Wgru = (const float*)d_in[3];
    const float* Ugru = (const float*)d_in[4];
    const float* bgru = (const float*)d_in[5];
    const float* Wang = (const float*)d_in[6];
    const float* bang = (const float*)d_in[7];
    const float* Wrad = (const float*)d_in[8];
    const float* brad = (const float*)d_in[9];
    float* out = (float*)d_out;

    // derive per-step keys on host (deterministic constants)
    uint32_t ka[NPTS][2], kr[NPTS][2];
#if PARTITIONABLE
    for (int t = 0; t < NPTS; t++) {
        uint32_t sk0, sk1;
        threefry2x32(0u, 42u, 0u, (uint32_t)t, sk0, sk1);     // split(key(42), 30)[t]
        threefry2x32(sk0, sk1, 0u, 0u, ka[t][0], ka[t][1]);   // split(key_t)[0]
        threefry2x32(sk0, sk1, 0u, 1u, kr[t][0], kr[t][1]);   // split(key_t)[1]
    }
#else
    uint32_t stepk[NPTS][2];
    orig_split(0u, 42u, NPTS, stepk);
    for (int t = 0; t < NPTS; t++) {
        uint32_t ch[2][2];
        orig_split(stepk[t][0], stepk[t][1], 2, ch);
        ka[t][0] = ch[0][0]; ka[t][1] = ch[0][1];
        kr[t][0] = ch[1][0]; kr[t][1] = ch[1][1];
    }
#endif

    float* hbase = nullptr;
    cudaGetSymbolAddress((void**)&hbase, g_h);

    precompute_kernel<<<dim3((G3 + 255) / 256, NCOLS + 1), 256>>>(Wenc, benc, Wgru, bgru);
    fill_wt_kernel<<<NPAD, 256>>>(Wang, bang, Wrad, brad);

    dim3 g1(UNITS / BN, BATCH / BM);     // (32, 64)
    int  g2 = BATCH / SR;                // 1024

    for (int t = 0; t < NPTS; t++) {
        const float* hin = (t == 0) ? s : (hbase + (size_t)((t - 1) & 1) * BATCH * UNITS);
        float* hout = hbase + (size_t)(t & 1) * BATCH * UNITS;
        gru_step_kernel<<<g1, 256>>>(hin, hout, Ugru, bgru, (t == 0) ? 1 : 0);
        sample_kernel<<<g2, 640>>>(hout, out, t,
                                   ka[t][0], ka[t][1], kr[t][0], kr[t][1]);
    }
}

// round 8
// speedup vs baseline: 1.4149x; 1.4149x over previous
#include <cuda_runtime.h>
#include <stdint.h>

// ======================= problem constants =======================
#define BATCH   8192
#define UNITS   1024
#define NPTS    30
#define AR      12
#define RR      64
#define NCOLS   76            // AR + RR
#define NPAD    80
#define G3      3072          // 3 * UNITS

// JAX threefry mode: 1 = partitionable (JAX >= 0.5 default), 0 = original
#define PARTITIONABLE 1

// output layout: concat(a_oh, a_prob, r_oh, r_prob), each [B, NPTS, C] row-major
#define AOH_BASE    0
#define APROB_BASE  (BATCH*NPTS*AR)                    // 2949120
#define ROH_BASE    (2*BATCH*NPTS*AR)                  // 5898240
#define RPROB_BASE  (2*BATCH*NPTS*AR + BATCH*NPTS*RR)  // 21626880

typedef unsigned long long u64;

// ======================= persistent device state =======================
__device__ float g_h[2ull * BATCH * UNITS];   // ping-pong hidden state
__device__ float g_P[NCOLS * G3];             // W_enc @ W_gru
__device__ float g_G[G3];                     // b_enc @ W_gru + b_gru
__device__ float g_Wt[NPAD * UNITS];          // transposed logits weights [80][1024]
__device__ float g_bt[NPAD];                  // concatenated bias [80]
__device__ int   g_aidx[BATCH];
__device__ int   g_ridx[BATCH];

// ======================= packed f32x2 helpers =======================
__device__ __forceinline__ u64 pack2(float lo, float hi) {
    u64 r;
    asm("mov.b64 %0, {%1, %2};" : "=l"(r) : "f"(lo), "f"(hi));
    return r;
}
__device__ __forceinline__ void fma2(u64& acc, u64 a, u64 b) {
    asm("fma.rn.f32x2 %0, %1, %2, %0;" : "+l"(acc) : "l"(a), "l"(b));
}
__device__ __forceinline__ float2 unpack2(u64 v) {
    float2 f;
    asm("mov.b64 {%0, %1}, %2;" : "=f"(f.x), "=f"(f.y) : "l"(v));
    return f;
}

// ======================= threefry-2x32 (20 rounds) =======================
__host__ __device__ __forceinline__ void threefry2x32(
    uint32_t k0, uint32_t k1, uint32_t x0, uint32_t x1,
    uint32_t& o0, uint32_t& o1)
{
    uint32_t ks2 = k0 ^ k1 ^ 0x1BD11BDAu;
    x0 += k0; x1 += k1;
#define TFR(r) { x0 += x1; x1 = (x1 << (r)) | (x1 >> (32 - (r))); x1 ^= x0; }
    TFR(13) TFR(15) TFR(26) TFR(6)   x0 += k1;  x1 += ks2 + 1u;
    TFR(17) TFR(29) TFR(16) TFR(24)  x0 += ks2; x1 += k0 + 2u;
    TFR(13) TFR(15) TFR(26) TFR(6)   x0 += k0;  x1 += k1 + 3u;
    TFR(17) TFR(29) TFR(16) TFR(24)  x0 += k1;  x1 += ks2 + 4u;
    TFR(13) TFR(15) TFR(26) TFR(6)   x0 += ks2; x1 += k0 + 5u;
#undef TFR
    o0 = x0; o1 = x1;
}

// ======================= precompute P and G (Kahan) =======================
__global__ void precompute_kernel(const float* __restrict__ Wenc,
                                  const float* __restrict__ benc,
                                  const float* __restrict__ Wgru,
                                  const float* __restrict__ bgru)
{
    int j = blockIdx.x * blockDim.x + threadIdx.x;   // 0..G3-1
    int g = blockIdx.y;                              // 0..NCOLS (last = G row)
    if (j >= G3) return;
    const float* arow = (g < NCOLS) ? (Wenc + (size_t)g * UNITS) : benc;
    float s = 0.f, c = 0.f;
    for (int k = 0; k < UNITS; k++) {
        float prod = arow[k] * Wgru[(size_t)k * G3 + j];
        float y = prod - c;
        float t = s + y;
        c = (t - s) - y;
        s = t;
    }
    if (g < NCOLS) g_P[(size_t)g * G3 + j] = s;
    else           g_G[j] = s + bgru[j];
}

// ======================= transpose logits weights (one-time) =======================
// g_Wt[x][k] = x<12 ? Wang[k][x] : x<76 ? Wrad[k][x-12] : 0
__global__ void fill_wt_kernel(const float* __restrict__ Wang, const float* __restrict__ bang,
                               const float* __restrict__ Wrad, const float* __restrict__ brad)
{
    const int x = blockIdx.x;                  // 0..79
    for (int k = threadIdx.x; k < UNITS; k += blockDim.x) {
        float v = 0.f;
        if (x < AR)         v = Wang[(size_t)k * AR + x];
        else if (x < NCOLS) v = Wrad[(size_t)k * RR + (x - AR)];
        g_Wt[(size_t)x * UNITS + k] = v;
    }
    if (threadIdx.x == 0) {
        float b = 0.f;
        if (x < AR)         b = bang[x];
        else if (x < NCOLS) b = brad[x - AR];
        g_bt[x] = b;
    }
}

// ======================= fused GEMM (h @ U_gru) + GRU cell =======================
// BM=128 x BN=32 x 3 gates, 256 threads, per-thread 8 rows x 2 cols x 3 gates.
// f32x2 pairs run along M: A row-pairs load directly as LDS.128 (broadcast),
// B values dup-packed on the ALU pipe. Double-buffered smem, 1 barrier/tile.
// NOTE: per-output-element accumulation is a single acc, ascending k -> the
// h bit-pattern is frozen; do not change the FMA order here.
#define BM 128
#define BN 32
#define KB 16

__global__ __launch_bounds__(256, 2)
void gru_step_kernel(const float* __restrict__ hin, float* __restrict__ hout,
                     const float* __restrict__ Ugru, const float* __restrict__ bgru,
                     int first)
{
    __shared__ __align__(16) float As[2][KB][BM];
    __shared__ __align__(16) float Bs[2][3][KB][BN];

    const int m0 = blockIdx.y * BM;
    const int j0 = blockIdx.x * BN;
    const int tid = threadIdx.x;
    const int tx = tid & 15;     // 0..15  -> 2 cols each
    const int ty = tid >> 4;     // 0..15  -> 8 rows each (4 f32x2 row-pairs)

    // acc[c][p]: c = gate*2 + n (6 cols), p = row-pair 0..3 (rows 2p, 2p+1)
    u64 acc[6][4];
#pragma unroll
    for (int c = 0; c < 6; c++)
#pragma unroll
        for (int p = 0; p < 4; p++) acc[c][p] = 0ull;

    // A-loader mapping: 2048 floats = 512 float4; thread loads 2 float4
    const int la_row = tid >> 2;         // 0..63
    const int la_kk  = (tid & 3) << 2;   // 0,4,8,12
    // B-loader mapping: per gate 512 floats = 256 float2; thread loads 1 float2/gate
    const int lb_kk = tid >> 4;          // 0..15
    const int lb_jj = (tid & 15) << 1;   // 0..30

    const float* pa0 = &hin[(size_t)(m0 + la_row) * UNITS + la_kk];
    const float* pa1 = &hin[(size_t)(m0 + la_row + 64) * UNITS + la_kk];
    const float* pb  = &Ugru[(size_t)lb_kk * G3 + j0 + lb_jj];

    // prologue: load tile 0 into buffer 0
    {
        float4 v0 = *(const float4*)pa0;
        float4 v1 = *(const float4*)pa1;
        As[0][la_kk + 0][la_row] = v0.x; As[0][la_kk + 1][la_row] = v0.y;
        As[0][la_kk + 2][la_row] = v0.z; As[0][la_kk + 3][la_row] = v0.w;
        As[0][la_kk + 0][la_row + 64] = v1.x; As[0][la_kk + 1][la_row + 64] = v1.y;
        As[0][la_kk + 2][la_row + 64] = v1.z; As[0][la_kk + 3][la_row + 64] = v1.w;
#pragma unroll
        for (int g = 0; g < 3; g++)
            *(float2*)&Bs[0][g][lb_kk][lb_jj] = *(const float2*)(pb + g * UNITS);
    }
    __syncthreads();

    const int NT = UNITS / KB;   // 64 tiles
    int cur = 0;
    for (int t = 0; t < NT; t++) {
        float4 va0, va1; float2 vb[3];
        const bool more = (t + 1 < NT);
        if (more) {
            const size_t koff = (size_t)(t + 1) * KB;
            va0 = *(const float4*)(pa0 + koff);
            va1 = *(const float4*)(pa1 + koff);
#pragma unroll
            for (int g = 0; g < 3; g++)
                vb[g] = *(const float2*)(pb + koff * G3 + g * UNITS);
        }

#pragma unroll
        for (int k = 0; k < KB; k++) {
            // A row-pairs: two LDS.128, broadcast within warp, no packs needed
            ulonglong2 a01 = *(const ulonglong2*)&As[cur][k][ty * 8];
            ulonglong2 a23 = *(const ulonglong2*)&As[cur][k][ty * 8 + 4];
            u64 a2[4] = { a01.x, a01.y, a23.x, a23.y };
            // B: one LDS.64 per gate + dup-pack each scalar (ALU pipe)
            u64 b2[6];
#pragma unroll
            for (int g = 0; g < 3; g++) {
                float2 b = *(const float2*)&Bs[cur][g][k][tx * 2];
                b2[g * 2 + 0] = pack2(b.x, b.x);
                b2[g * 2 + 1] = pack2(b.y, b.y);
            }
#pragma unroll
            for (int c = 0; c < 6; c++)
#pragma unroll
                for (int p = 0; p < 4; p++)
                    fma2(acc[c][p], a2[p], b2[c]);
        }

        if (more) {
            const int nxt = cur ^ 1;
            As[nxt][la_kk + 0][la_row] = va0.x; As[nxt][la_kk + 1][la_row] = va0.y;
            As[nxt][la_kk + 2][la_row] = va0.z; As[nxt][la_kk + 3][la_row] = va0.w;
            As[nxt][la_kk + 0][la_row + 64] = va1.x; As[nxt][la_kk + 1][la_row + 64] = va1.y;
            As[nxt][la_kk + 2][la_row + 64] = va1.z; As[nxt][la_kk + 3][la_row + 64] = va1.w;
#pragma unroll
            for (int g = 0; g < 3; g++)
                *(float2*)&Bs[nxt][g][lb_kk][lb_jj] = vb[g];
            __syncthreads();
            cur = nxt;
        }
    }

    // epilogue: gx gather (vectorized float2) + GRU cell
    const int jb = j0 + tx * 2;
#pragma unroll
    for (int p = 0; p < 4; p++) {
        float2 vz[2] = { unpack2(acc[0][p]), unpack2(acc[1][p]) };
        float2 vr[2] = { unpack2(acc[2][p]), unpack2(acc[3][p]) };
        float2 vn[2] = { unpack2(acc[4][p]), unpack2(acc[5][p]) };
#pragma unroll
        for (int rr = 0; rr < 2; rr++) {
            const int row = m0 + ty * 8 + p * 2 + rr;
            const float az0 = rr ? vz[0].y : vz[0].x;
            const float az1 = rr ? vz[1].y : vz[1].x;
            const float ar0 = rr ? vr[0].y : vr[0].x;
            const float ar1 = rr ? vr[1].y : vr[1].x;
            const float an0 = rr ? vn[0].y : vn[0].x;
            const float an1 = rr ? vn[1].y : vn[1].x;

            float2 pz, pr, pn;
            if (first) {
                pz = *(const float2*)&bgru[jb];
                pr = *(const float2*)&bgru[UNITS + jb];
                pn = *(const float2*)&bgru[2 * UNITS + jb];
            } else {
                const float* Pa = g_P + (size_t)g_aidx[row] * G3;
                const float* Pr = g_P + (size_t)(AR + g_ridx[row]) * G3;
                float2 a, b, c;
                a = *(const float2*)&Pa[jb];
                b = *(const float2*)&Pr[jb];
                c = *(const float2*)&g_G[jb];
                pz.x = a.x + b.x + c.x; pz.y = a.y + b.y + c.y;
                a = *(const float2*)&Pa[UNITS + jb];
                b = *(const float2*)&Pr[UNITS + jb];
                c = *(const float2*)&g_G[UNITS + jb];
                pr.x = a.x + b.x + c.x; pr.y = a.y + b.y + c.y;
                a = *(const float2*)&Pa[2 * UNITS + jb];
                b = *(const float2*)&Pr[2 * UNITS + jb];
                c = *(const float2*)&g_G[2 * UNITS + jb];
                pn.x = a.x + b.x + c.x; pn.y = a.y + b.y + c.y;
            }
            const float2 hp = *(const float2*)&hin[(size_t)row * UNITS + jb];
            const float z0 = 1.f / (1.f + expf(-(pz.x + az0)));
            const float z1 = 1.f / (1.f + expf(-(pz.y + az1)));
            const float r0 = 1.f / (1.f + expf(-(pr.x + ar0)));
            const float r1 = 1.f / (1.f + expf(-(pr.y + ar1)));
            const float n0 = tanhf(pn.x + r0 * an0);
            const float n1 = tanhf(pn.y + r1 * an1);
            float2 o;
            o.x = z0 * hp.x + (1.f - z0) * n0;
            o.y = z1 * hp.y + (1.f - z1) * n1;
            *(float2*)&hout[(size_t)row * UNITS + jb] = o;
        }
    }
}

// ======================= sampling kernel =======================
// One block handles R=8 rows. 640 threads mapped y-major: x = tid/8 (weight
// row), y = tid&7 (batch row). Warp lanes span 8 y x 4 x -> g_Wt loads are
// 4 distinct addresses/warp (broadcast dedup), hs rows padded to 1028 floats
// so the 8 distinct LDS.128 rows hit distinct bank groups (conflict-free).
// The fmaf accumulation sequence is bit-identical to the reference ordering.
#define SR 8
#define HSP (UNITS + 4)

__global__ __launch_bounds__(640)
void sample_kernel(const float* __restrict__ h,
                   float* __restrict__ out, int t,
                   uint32_t ka0, uint32_t ka1, uint32_t kr0, uint32_t kr1)
{
    __shared__ __align__(16) float hs[SR][HSP];
    __shared__ float lg[SR][NCOLS];
    __shared__ float es[SR][NCOLS];
    __shared__ float pl[SR][NCOLS];
    __shared__ float mx[SR][2];
    __shared__ float sm[SR][2];
    __shared__ int   sidx[SR][2];

    const int tid  = threadIdx.x;
    const int row0 = blockIdx.x * SR;
    const int x = tid >> 3;     // 0..79  (weight row)
    const int y = tid & 7;      // 0..7   (batch row)

    // stage h rows into smem (padded rows)
    for (int i = tid; i < SR * UNITS / 4; i += blockDim.x) {
        int r = i >> 8;            // /256 (=1024/4)
        int c = (i & 255) << 2;
        *(float4*)&hs[r][c] = *(const float4*)&h[(size_t)(row0 + r) * UNITS + c];
    }
    __syncthreads();

    if (x < NCOLS) {
        // logits: dot(h_row, Wt row) with 4-way partial sums (bit-exact vs reference)
        const float* wt = g_Wt + (size_t)x * UNITS;
        float a0 = 0.f, a1 = 0.f, a2 = 0.f, a3 = 0.f;
#pragma unroll 4
        for (int k = 0; k < UNITS; k += 4) {
            float4 w4 = *(const float4*)&wt[k];
            float4 h4 = *(const float4*)&hs[y][k];
            a0 = fmaf(h4.x, w4.x, a0);
            a1 = fmaf(h4.y, w4.y, a1);
            a2 = fmaf(h4.z, w4.z, a2);
            a3 = fmaf(h4.w, w4.w, a3);
        }
        float l = ((a0 + a1) + (a2 + a3)) + g_bt[x];
        lg[y][x] = l;

        // gumbel noise, exact JAX formula
        const int row = row0 + y;
        uint32_t key0, key1, bits;
#if PARTITIONABLE
        uint32_t f = (x < AR) ? (uint32_t)(row * AR + x) : (uint32_t)(row * RR + (x - AR));
        if (x < AR) { key0 = ka0; key1 = ka1; } else { key0 = kr0; key1 = kr1; }
        uint32_t o0, o1;
        threefry2x32(key0, key1, 0u, f, o0, o1);
        bits = o0 ^ o1;
#else
        uint32_t f, half;
        if (x < AR) { f = (uint32_t)(row * AR + x);        half = (uint32_t)(BATCH * AR / 2); key0 = ka0; key1 = ka1; }
        else        { f = (uint32_t)(row * RR + (x - AR)); half = (uint32_t)(BATCH * RR / 2); key0 = kr0; key1 = kr1; }
        uint32_t j = (f < half) ? f : (f - half);
        uint32_t o0, o1;
        threefry2x32(key0, key1, j, j + half, o0, o1);
        bits = (f < half) ? o0 : o1;
#endif
        const float TINY = 1.17549435e-38f;
        float fl = __uint_as_float((bits >> 9) | 0x3f800000u) - 1.0f;
        float uu = fmaxf(TINY, fl + TINY);
        float gum = -logf(-logf(uu));
        pl[y][x] = gum + l;
    }
    __syncthreads();

    // per-row reductions (max logit for softmax; first-occurrence argmax of logits+gumbel)
    if (x == 0) {
        float m = lg[y][0];
        for (int i = 1; i < AR; i++) m = fmaxf(m, lg[y][i]);
        mx[y][0] = m;
        float best = pl[y][0]; int bi = 0;
        for (int i = 1; i < AR; i++) if (pl[y][i] > best) { best = pl[y][i]; bi = i; }
        sidx[y][0] = bi;
    } else if (x == 1) {
        float m = lg[y][AR];
        for (int i = AR + 1; i < NCOLS; i++) m = fmaxf(m, lg[y][i]);
        mx[y][1] = m;
        float best = pl[y][AR]; int bi = 0;
        for (int i = AR + 1; i < NCOLS; i++) if (pl[y][i] > best) { best = pl[y][i]; bi = i - AR; }
        sidx[y][1] = bi;
    }
    __syncthreads();

    if (x < NCOLS) es[y][x] = expf(lg[y][x] - mx[y][(x < AR) ? 0 : 1]);
    __syncthreads();

    if (x == 0) { float s = 0.f; for (int i = 0;  i < AR;    i++) s += es[y][i]; sm[y][0] = s; }
    else if (x == 1) { float s = 0.f; for (int i = AR; i < NCOLS; i++) s += es[y][i]; sm[y][1] = s; }
    __syncthreads();

    const int row = row0 + y;
    if (x < AR) {
        size_t o = (size_t)(row * NPTS + t) * AR + x;
        out[AOH_BASE   + o] = (x == sidx[y][0]) ? 1.0f : 0.0f;
        out[APROB_BASE + o] = es[y][x] / sm[y][0];
    } else if (x < NCOLS) {
        int c = x - AR;
        size_t o = (size_t)(row * NPTS + t) * RR + c;
        out[ROH_BASE   + o] = (c == sidx[y][1]) ? 1.0f : 0.0f;
        out[RPROB_BASE + o] = es[y][x] / sm[y][1];
    }
    if (x == 0) g_aidx[row] = sidx[y][0];
    if (x == 1) g_ridx[row] = sidx[y][1];
}

// ======================= host-side key derivation =======================
#if !PARTITIONABLE
static void orig_split(uint32_t k0, uint32_t k1, int n, uint32_t out[][2])
{
    uint32_t y0[64], y1[64];
    for (int j = 0; j < n; j++)
        threefry2x32(k0, k1, (uint32_t)j, (uint32_t)(n + j), y0[j], y1[j]);
    for (int t = 0; t < n; t++) {
        int i0 = 2 * t, i1 = 2 * t + 1;
        out[t][0] = (i0 < n) ? y0[i0] : y1[i0 - n];
        out[t][1] = (i1 < n) ? y0[i1] : y1[i1 - n];
    }
}
#endif

// ======================= launcher =======================
extern "C" void kernel_launch(void* const* d_in, const int* in_sizes, int n_in,
                              void* d_out, int out_size)
{
    const float* s    = (const float*)d_in[0];
    const float* Wenc = (const float*)d_in[1];
    const float* benc = (const float*)d_in[2];
    const float* Wgru = (const float*)d_in[3];
    const float* Ugru = (const float*)d_in[4];
    const float* bgru = (const float*)d_in[5];
    const float* Wang = (const float*)d_in[6];
    const float* bang = (const float*)d_in[7];
    const float* Wrad = (const float*)d_in[8];
    const float* brad = (const float*)d_in[9];
    float* out = (float*)d_out;

    // derive per-step keys on host (deterministic constants)
    uint32_t ka[NPTS][2], kr[NPTS][2];
#if PARTITIONABLE
    for (int t = 0; t < NPTS; t++) {
        uint32_t sk0, sk1;
        threefry2x32(0u, 42u, 0u, (uint32_t)t, sk0, sk1);     // split(key(42), 30)[t]
        threefry2x32(sk0, sk1, 0u, 0u, ka[t][0], ka[t][1]);   // split(key_t)[0]
        threefry2x32(sk0, sk1, 0u, 1u, kr[t][0], kr[t][1]);   // split(key_t)[1]
    }
#else
    uint32_t stepk[NPTS][2];
    orig_split(0u, 42u, NPTS, stepk);
    for (int t = 0; t < NPTS; t++) {
        uint32_t ch[2][2];
        orig_split(stepk[t][0], stepk[t][1], 2, ch);
        ka[t][0] = ch[0][0]; ka[t][1] = ch[0][1];
        kr[t][0] = ch[1][0]; kr[t][1] = ch[1][1];
    }
#endif

    float* hbase = nullptr;
    cudaGetSymbolAddress((void**)&hbase, g_h);

    precompute_kernel<<<dim3((G3 + 255) / 256, NCOLS + 1), 256>>>(Wenc, benc, Wgru, bgru);
    fill_wt_kernel<<<NPAD, 256>>>(Wang, bang, Wrad, brad);

    dim3 g1(UNITS / BN, BATCH / BM);     // (32, 64)
    int  g2 = BATCH / SR;                // 1024

    for (int t = 0; t < NPTS; t++) {
        const float* hin = (t == 0) ? s : (hbase + (size_t)((t - 1) & 1) * BATCH * UNITS);
        float* hout = hbase + (size_t)(t & 1) * BATCH * UNITS;
        gru_step_kernel<<<g1, 256>>>(hin, hout, Ugru, bgru, (t == 0) ? 1 : 0);
        sample_kernel<<<g2, 640>>>(hout, out, t,
                                   ka[t][0], ka[t][1], kr[t][0], kr[t][1]);
    }
}

// round 9
// speedup vs baseline: 1.4354x; 1.0145x over previous
#include <cuda_runtime.h>
#include <stdint.h>

// ======================= problem constants =======================
#define BATCH   8192
#define UNITS   1024
#define NPTS    30
#define AR      12
#define RR      64
#define NCOLS   76            // AR + RR
#define NPAD    80
#define G3      3072          // 3 * UNITS

// JAX threefry mode: 1 = partitionable (JAX >= 0.5 default), 0 = original
#define PARTITIONABLE 1

// output layout: concat(a_oh, a_prob, r_oh, r_prob), each [B, NPTS, C] row-major
#define AOH_BASE    0
#define APROB_BASE  (BATCH*NPTS*AR)                    // 2949120
#define ROH_BASE    (2*BATCH*NPTS*AR)                  // 5898240
#define RPROB_BASE  (2*BATCH*NPTS*AR + BATCH*NPTS*RR)  // 21626880

typedef unsigned long long u64;

// ======================= persistent device state =======================
__device__ float g_h[2ull * BATCH * UNITS];   // ping-pong hidden state
__device__ float g_P[NCOLS * G3];             // W_enc @ W_gru
__device__ float g_G[G3];                     // b_enc @ W_gru + b_gru
__device__ float g_Wt2[(UNITS/4) * NPAD * 4]; // logits weights, [k/4][x][4] chunked layout
__device__ float g_bt[NPAD];                  // concatenated bias [80]
__device__ int   g_aidx[BATCH];
__device__ int   g_ridx[BATCH];

// ======================= packed f32x2 helpers =======================
__device__ __forceinline__ u64 pack2(float lo, float hi) {
    u64 r;
    asm("mov.b64 %0, {%1, %2};" : "=l"(r) : "f"(lo), "f"(hi));
    return r;
}
__device__ __forceinline__ void fma2(u64& acc, u64 a, u64 b) {
    asm("fma.rn.f32x2 %0, %1, %2, %0;" : "+l"(acc) : "l"(a), "l"(b));
}
__device__ __forceinline__ float2 unpack2(u64 v) {
    float2 f;
    asm("mov.b64 {%0, %1}, %2;" : "=f"(f.x), "=f"(f.y) : "l"(v));
    return f;
}

// ======================= threefry-2x32 (20 rounds) =======================
__host__ __device__ __forceinline__ void threefry2x32(
    uint32_t k0, uint32_t k1, uint32_t x0, uint32_t x1,
    uint32_t& o0, uint32_t& o1)
{
    uint32_t ks2 = k0 ^ k1 ^ 0x1BD11BDAu;
    x0 += k0; x1 += k1;
#define TFR(r) { x0 += x1; x1 = (x1 << (r)) | (x1 >> (32 - (r))); x1 ^= x0; }
    TFR(13) TFR(15) TFR(26) TFR(6)   x0 += k1;  x1 += ks2 + 1u;
    TFR(17) TFR(29) TFR(16) TFR(24)  x0 += ks2; x1 += k0 + 2u;
    TFR(13) TFR(15) TFR(26) TFR(6)   x0 += k0;  x1 += k1 + 3u;
    TFR(17) TFR(29) TFR(16) TFR(24)  x0 += k1;  x1 += ks2 + 4u;
    TFR(13) TFR(15) TFR(26) TFR(6)   x0 += ks2; x1 += k0 + 5u;
#undef TFR
    o0 = x0; o1 = x1;
}

// ======================= precompute P and G (Kahan) =======================
__global__ void precompute_kernel(const float* __restrict__ Wenc,
                                  const float* __restrict__ benc,
                                  const float* __restrict__ Wgru,
                                  const float* __restrict__ bgru)
{
    int j = blockIdx.x * blockDim.x + threadIdx.x;   // 0..G3-1
    int g = blockIdx.y;                              // 0..NCOLS (last = G row)
    if (j >= G3) return;
    const float* arow = (g < NCOLS) ? (Wenc + (size_t)g * UNITS) : benc;
    float s = 0.f, c = 0.f;
    for (int k = 0; k < UNITS; k++) {
        float prod = arow[k] * Wgru[(size_t)k * G3 + j];
        float y = prod - c;
        float t = s + y;
        c = (t - s) - y;
        s = t;
    }
    if (g < NCOLS) g_P[(size_t)g * G3 + j] = s;
    else           g_G[j] = s + bgru[j];
}

// ======================= pack logits weights (one-time) =======================
// g_Wt2[(k/4)*NPAD*4 + x*4 + (k%4)] = x<12 ? Wang[k][x] : x<76 ? Wrad[k][x-12] : 0
__global__ void fill_wt_kernel(const float* __restrict__ Wang, const float* __restrict__ bang,
                               const float* __restrict__ Wrad, const float* __restrict__ brad)
{
    const int x = blockIdx.x;                  // 0..79
    for (int k = threadIdx.x; k < UNITS; k += blockDim.x) {
        float v = 0.f;
        if (x < AR)         v = Wang[(size_t)k * AR + x];
        else if (x < NCOLS) v = Wrad[(size_t)k * RR + (x - AR)];
        g_Wt2[(size_t)((k >> 2) * NPAD + x) * 4 + (k & 3)] = v;
    }
    if (threadIdx.x == 0) {
        float b = 0.f;
        if (x < AR)         b = bang[x];
        else if (x < NCOLS) b = brad[x - AR];
        g_bt[x] = b;
    }
}

// ======================= fused GEMM (h @ U_gru) + GRU cell =======================
// BM=128 x BN=32 x 3 gates, 256 threads, per-thread 8 rows x 2 cols x 3 gates.
// f32x2 pairs run along M. As row stride padded to 132 floats so A-staging
// STS.32 banks go 2-way instead of 4-way (Dbank per k-step = 16).
// NOTE: per-output-element accumulation is a single acc, ascending k -> the
// h bit-pattern is frozen; do not change the FMA order here.
#define BM 128
#define BMP 132
#define BN 32
#define KB 16

__global__ __launch_bounds__(256, 2)
void gru_step_kernel(const float* __restrict__ hin, float* __restrict__ hout,
                     const float* __restrict__ Ugru, const float* __restrict__ bgru,
                     int first)
{
    __shared__ __align__(16) float As[2][KB][BMP];
    __shared__ __align__(16) float Bs[2][3][KB][BN];

    const int m0 = blockIdx.y * BM;
    const int j0 = blockIdx.x * BN;
    const int tid = threadIdx.x;
    const int tx = tid & 15;     // 0..15  -> 2 cols each
    const int ty = tid >> 4;     // 0..15  -> 8 rows each (4 f32x2 row-pairs)

    // acc[c][p]: c = gate*2 + n (6 cols), p = row-pair 0..3 (rows 2p, 2p+1)
    u64 acc[6][4];
#pragma unroll
    for (int c = 0; c < 6; c++)
#pragma unroll
        for (int p = 0; p < 4; p++) acc[c][p] = 0ull;

    // A-loader mapping: 2048 floats = 512 float4; thread loads 2 float4
    const int la_row = tid >> 2;         // 0..63
    const int la_kk  = (tid & 3) << 2;   // 0,4,8,12
    // B-loader mapping: per gate 512 floats = 256 float2; thread loads 1 float2/gate
    const int lb_kk = tid >> 4;          // 0..15
    const int lb_jj = (tid & 15) << 1;   // 0..30

    const float* pa0 = &hin[(size_t)(m0 + la_row) * UNITS + la_kk];
    const float* pa1 = &hin[(size_t)(m0 + la_row + 64) * UNITS + la_kk];
    const float* pb  = &Ugru[(size_t)lb_kk * G3 + j0 + lb_jj];

    // prologue: load tile 0 into buffer 0
    {
        float4 v0 = *(const float4*)pa0;
        float4 v1 = *(const float4*)pa1;
        As[0][la_kk + 0][la_row] = v0.x; As[0][la_kk + 1][la_row] = v0.y;
        As[0][la_kk + 2][la_row] = v0.z; As[0][la_kk + 3][la_row] = v0.w;
        As[0][la_kk + 0][la_row + 64] = v1.x; As[0][la_kk + 1][la_row + 64] = v1.y;
        As[0][la_kk + 2][la_row + 64] = v1.z; As[0][la_kk + 3][la_row + 64] = v1.w;
#pragma unroll
        for (int g = 0; g < 3; g++)
            *(float2*)&Bs[0][g][lb_kk][lb_jj] = *(const float2*)(pb + g * UNITS);
    }
    __syncthreads();

    const int NT = UNITS / KB;   // 64 tiles
    int cur = 0;
    for (int t = 0; t < NT; t++) {
        float4 va0, va1; float2 vb[3];
        const bool more = (t + 1 < NT);
        if (more) {
            const size_t koff = (size_t)(t + 1) * KB;
            va0 = *(const float4*)(pa0 + koff);
            va1 = *(const float4*)(pa1 + koff);
#pragma unroll
            for (int g = 0; g < 3; g++)
                vb[g] = *(const float2*)(pb + koff * G3 + g * UNITS);
        }

#pragma unroll
        for (int k = 0; k < KB; k++) {
            // A row-pairs: two LDS.128, broadcast within warp, no packs needed
            ulonglong2 a01 = *(const ulonglong2*)&As[cur][k][ty * 8];
            ulonglong2 a23 = *(const ulonglong2*)&As[cur][k][ty * 8 + 4];
            u64 a2[4] = { a01.x, a01.y, a23.x, a23.y };
            // B: one LDS.64 per gate + dup-pack each scalar (ALU pipe)
            u64 b2[6];
#pragma unroll
            for (int g = 0; g < 3; g++) {
                float2 b = *(const float2*)&Bs[cur][g][k][tx * 2];
                b2[g * 2 + 0] = pack2(b.x, b.x);
                b2[g * 2 + 1] = pack2(b.y, b.y);
            }
#pragma unroll
            for (int c = 0; c < 6; c++)
#pragma unroll
                for (int p = 0; p < 4; p++)
                    fma2(acc[c][p], a2[p], b2[c]);
        }

        if (more) {
            const int nxt = cur ^ 1;
            As[nxt][la_kk + 0][la_row] = va0.x; As[nxt][la_kk + 1][la_row] = va0.y;
            As[nxt][la_kk + 2][la_row] = va0.z; As[nxt][la_kk + 3][la_row] = va0.w;
            As[nxt][la_kk + 0][la_row + 64] = va1.x; As[nxt][la_kk + 1][la_row + 64] = va1.y;
            As[nxt][la_kk + 2][la_row + 64] = va1.z; As[nxt][la_kk + 3][la_row + 64] = va1.w;
#pragma unroll
            for (int g = 0; g < 3; g++)
                *(float2*)&Bs[nxt][g][lb_kk][lb_jj] = vb[g];
            __syncthreads();
            cur = nxt;
        }
    }

    // epilogue: gx gather (vectorized float2) + GRU cell
    const int jb = j0 + tx * 2;
#pragma unroll
    for (int p = 0; p < 4; p++) {
        float2 vz[2] = { unpack2(acc[0][p]), unpack2(acc[1][p]) };
        float2 vr[2] = { unpack2(acc[2][p]), unpack2(acc[3][p]) };
        float2 vn[2] = { unpack2(acc[4][p]), unpack2(acc[5][p]) };
#pragma unroll
        for (int rr = 0; rr < 2; rr++) {
            const int row = m0 + ty * 8 + p * 2 + rr;
            const float az0 = rr ? vz[0].y : vz[0].x;
            const float az1 = rr ? vz[1].y : vz[1].x;
            const float ar0 = rr ? vr[0].y : vr[0].x;
            const float ar1 = rr ? vr[1].y : vr[1].x;
            const float an0 = rr ? vn[0].y : vn[0].x;
            const float an1 = rr ? vn[1].y : vn[1].x;

            float2 pz, pr, pn;
            if (first) {
                pz = *(const float2*)&bgru[jb];
                pr = *(const float2*)&bgru[UNITS + jb];
                pn = *(const float2*)&bgru[2 * UNITS + jb];
            } else {
                const float* Pa = g_P + (size_t)g_aidx[row] * G3;
                const float* Pr = g_P + (size_t)(AR + g_ridx[row]) * G3;
                float2 a, b, c;
                a = *(const float2*)&Pa[jb];
                b = *(const float2*)&Pr[jb];
                c = *(const float2*)&g_G[jb];
                pz.x = a.x + b.x + c.x; pz.y = a.y + b.y + c.y;
                a = *(const float2*)&Pa[UNITS + jb];
                b = *(const float2*)&Pr[UNITS + jb];
                c = *(const float2*)&g_G[UNITS + jb];
                pr.x = a.x + b.x + c.x; pr.y = a.y + b.y + c.y;
                a = *(const float2*)&Pa[2 * UNITS + jb];
                b = *(const float2*)&Pr[2 * UNITS + jb];
                c = *(const float2*)&g_G[2 * UNITS + jb];
                pn.x = a.x + b.x + c.x; pn.y = a.y + b.y + c.y;
            }
            const float2 hp = *(const float2*)&hin[(size_t)row * UNITS + jb];
            const float z0 = 1.f / (1.f + expf(-(pz.x + az0)));
            const float z1 = 1.f / (1.f + expf(-(pz.y + az1)));
            const float r0 = 1.f / (1.f + expf(-(pr.x + ar0)));
            const float r1 = 1.f / (1.f + expf(-(pr.y + ar1)));
            const float n0 = tanhf(pn.x + r0 * an0);
            const float n1 = tanhf(pn.y + r1 * an1);
            float2 o;
            o.x = z0 * hp.x + (1.f - z0) * n0;
            o.y = z1 * hp.y + (1.f - z1) * n1;
            *(float2*)&hout[(size_t)row * UNITS + jb] = o;
        }
    }
}

// ======================= sampling kernel =======================
// One block handles R=8 rows. 640 threads mapped y-major: x = tid/8 (weight
// row), y = tid&7 (batch row). Weights in chunked layout g_Wt2[k/4][x][4]:
// a warp's 4 x-values read 64 contiguous bytes (1 line, broadcast dedup).
// hs rows padded so the 8 distinct LDS.128 rows are bank-conflict-free.
// The fmaf accumulation sequence is bit-identical to the reference ordering.
#define SR 8
#define HSP (UNITS + 4)

__global__ __launch_bounds__(640)
void sample_kernel(const float* __restrict__ h,
                   float* __restrict__ out, int t,
                   uint32_t ka0, uint32_t ka1, uint32_t kr0, uint32_t kr1)
{
    __shared__ __align__(16) float hs[SR][HSP];
    __shared__ float lg[SR][NCOLS];
    __shared__ float es[SR][NCOLS];
    __shared__ float pl[SR][NCOLS];
    __shared__ float mx[SR][2];
    __shared__ float sm[SR][2];
    __shared__ int   sidx[SR][2];

    const int tid  = threadIdx.x;
    const int row0 = blockIdx.x * SR;
    const int x = tid >> 3;     // 0..79  (weight row)
    const int y = tid & 7;      // 0..7   (batch row)

    // stage h rows into smem (padded rows)
    for (int i = tid; i < SR * UNITS / 4; i += blockDim.x) {
        int r = i >> 8;            // /256 (=1024/4)
        int c = (i & 255) << 2;
        *(float4*)&hs[r][c] = *(const float4*)&h[(size_t)(row0 + r) * UNITS + c];
    }
    __syncthreads();

    if (x < NCOLS) {
        // logits: dot(h_row, Wt row) with 4-way partial sums (bit-exact vs reference)
        float a0 = 0.f, a1 = 0.f, a2 = 0.f, a3 = 0.f;
#pragma unroll 4
        for (int k = 0; k < UNITS; k += 4) {
            float4 w4 = *(const float4*)&g_Wt2[(size_t)((k >> 2) * NPAD + x) * 4];
            float4 h4 = *(const float4*)&hs[y][k];
            a0 = fmaf(h4.x, w4.x, a0);
            a1 = fmaf(h4.y, w4.y, a1);
            a2 = fmaf(h4.z, w4.z, a2);
            a3 = fmaf(h4.w, w4.w, a3);
        }
        float l = ((a0 + a1) + (a2 + a3)) + g_bt[x];
        lg[y][x] = l;

        // gumbel noise, exact JAX formula
        const int row = row0 + y;
        uint32_t key0, key1, bits;
#if PARTITIONABLE
        uint32_t f = (x < AR) ? (uint32_t)(row * AR + x) : (uint32_t)(row * RR + (x - AR));
        if (x < AR) { key0 = ka0; key1 = ka1; } else { key0 = kr0; key1 = kr1; }
        uint32_t o0, o1;
        threefry2x32(key0, key1, 0u, f, o0, o1);
        bits = o0 ^ o1;
#else
        uint32_t f, half;
        if (x < AR) { f = (uint32_t)(row * AR + x);        half = (uint32_t)(BATCH * AR / 2); key0 = ka0; key1 = ka1; }
        else        { f = (uint32_t)(row * RR + (x - AR)); half = (uint32_t)(BATCH * RR / 2); key0 = kr0; key1 = kr1; }
        uint32_t j = (f < half) ? f : (f - half);
        uint32_t o0, o1;
        threefry2x32(key0, key1, j, j + half, o0, o1);
        bits = (f < half) ? o0 : o1;
#endif
        const float TINY = 1.17549435e-38f;
        float fl = __uint_as_float((bits >> 9) | 0x3f800000u) - 1.0f;
        float uu = fmaxf(TINY, fl + TINY);
        float gum = -logf(-logf(uu));
        pl[y][x] = gum + l;
    }
    __syncthreads();

    // per-row reductions (max logit for softmax; first-occurrence argmax of logits+gumbel)
    if (x == 0) {
        float m = lg[y][0];
        for (int i = 1; i < AR; i++) m = fmaxf(m, lg[y][i]);
        mx[y][0] = m;
        float best = pl[y][0]; int bi = 0;
        for (int i = 1; i < AR; i++) if (pl[y][i] > best) { best = pl[y][i]; bi = i; }
        sidx[y][0] = bi;
    } else if (x == 1) {
        float m = lg[y][AR];
        for (int i = AR + 1; i < NCOLS; i++) m = fmaxf(m, lg[y][i]);
        mx[y][1] = m;
        float best = pl[y][AR]; int bi = 0;
        for (int i = AR + 1; i < NCOLS; i++) if (pl[y][i] > best) { best = pl[y][i]; bi = i - AR; }
        sidx[y][1] = bi;
    }
    __syncthreads();

    if (x < NCOLS) es[y][x] = expf(lg[y][x] - mx[y][(x < AR) ? 0 : 1]);
    __syncthreads();

    if (x == 0) { float s = 0.f; for (int i = 0;  i < AR;    i++) s += es[y][i]; sm[y][0] = s; }
    else if (x == 1) { float s = 0.f; for (int i = AR; i < NCOLS; i++) s += es[y][i]; sm[y][1] = s; }
    __syncthreads();

    const int row = row0 + y;
    if (x < AR) {
        size_t o = (size_t)(row * NPTS + t) * AR + x;
        out[AOH_BASE   + o] = (x == sidx[y][0]) ? 1.0f : 0.0f;
        out[APROB_BASE + o] = es[y][x] / sm[y][0];
    } else if (x < NCOLS) {
        int c = x - AR;
        size_t o = (size_t)(row * NPTS + t) * RR + c;
        out[ROH_BASE   + o] = (c == sidx[y][1]) ? 1.0f : 0.0f;
        out[RPROB_BASE + o] = es[y][x] / sm[y][1];
    }
    if (x == 0) g_aidx[row] = sidx[y][0];
    if (x == 1) g_ridx[row] = sidx[y][1];
}

// ======================= host-side key derivation =======================
#if !PARTITIONABLE
static void orig_split(uint32_t k0, uint32_t k1, int n, uint32_t out[][2])
{
    uint32_t y0[64], y1[64];
    for (int j = 0; j < n; j++)
        threefry2x32(k0, k1, (uint32_t)j, (uint32_t)(n + j), y0[j], y1[j]);
    for (int t = 0; t < n; t++) {
        int i0 = 2 * t, i1 = 2 * t + 1;
        out[t][0] = (i0 < n) ? y0[i0] : y1[i0 - n];
        out[t][1] = (i1 < n) ? y0[i1] : y1[i1 - n];
    }
}
#endif

// ======================= launcher =======================
extern "C" void kernel_launch(void* const* d_in, const int* in_sizes, int n_in,
                              void* d_out, int out_size)
{
    const float* s    = (const float*)d_in[0];
    const float* Wenc = (const float*)d_in[1];
    const float* benc = (const float*)d_in[2];
    const float* Wgru = (const float*)d_in[3];
    const float* Ugru = (const float*)d_in[4];
    const float* bgru = (const float*)d_in[5];
    const float* Wang = (const float*)d_in[6];
    const float* bang = (const float*)d_in[7];
    const float* Wrad = (const float*)d_in[8];
    const float* brad = (const float*)d_in[9];
    float* out = (float*)d_out;

    // derive per-step keys on host (deterministic constants)
    uint32_t ka[NPTS][2], kr[NPTS][2];
#if PARTITIONABLE
    for (int t = 0; t < NPTS; t++) {
        uint32_t sk0, sk1;
        threefry2x32(0u, 42u, 0u, (uint32_t)t, sk0, sk1);     // split(key(42), 30)[t]
        threefry2x32(sk0, sk1, 0u, 0u, ka[t][0], ka[t][1]);   // split(key_t)[0]
        threefry2x32(sk0, sk1, 0u, 1u, kr[t][0], kr[t][1]);   // split(key_t)[1]
    }
#else
    uint32_t stepk[NPTS][2];
    orig_split(0u, 42u, NPTS, stepk);
    for (int t = 0; t < NPTS; t++) {
        uint32_t ch[2][2];
        orig_split(stepk[t][0], stepk[t][1], 2, ch);
        ka[t][0] = ch[0][0]; ka[t][1] = ch[0][1];
        kr[t][0] = ch[1][0]; kr[t][1] = ch[1][1];
    }
#endif

    float* hbase = nullptr;
    cudaGetSymbolAddress((void**)&hbase, g_h);

    precompute_kernel<<<dim3((G3 + 255) / 256, NCOLS + 1), 256>>>(Wenc, benc, Wgru, bgru);
    fill_wt_kernel<<<NPAD, 256>>>(Wang, bang, Wrad, brad);

    dim3 g1(UNITS / BN, BATCH / BM);     // (32, 64)
    int  g2 = BATCH / SR;                // 1024

    for (int t = 0; t < NPTS; t++) {
        const float* hin = (t == 0) ? s : (hbase + (size_t)((t - 1) & 1) * BATCH * UNITS);
        float* hout = hbase + (size_t)(t & 1) * BATCH * UNITS;
        gru_step_kernel<<<g1, 256>>>(hin, hout, Ugru, bgru, (t == 0) ? 1 : 0);
        sample_kernel<<<g2, 640>>>(hout, out, t,
                                   ka[t][0], ka[t][1], kr[t][0], kr[t][1]);
    }
}